// round 1
// baseline (speedup 1.0000x reference)
#include <cuda_runtime.h>
#include <cuda_bf16.h>

// Problem constants
#define B_    512
#define S_    128
#define H_    768
#define NW_   51
#define INTENT_ 22
#define SLOT_ 122

// Slot GEMM tiling
#define BM 64
#define BN 128
#define BK 16
#define AS_STRIDE 68   // padded stride for conflict-free frag loads

#define M_TOTAL (B_ * NW_)          // 26112
#define OUT_ID_ELEMS (B_ * INTENT_) // 11264

// ---------------------------------------------------------------------------
// Intent head: res_id = pooled @ W_id + b_id   [512, 22]
// One block per batch row, one warp per output column.
// ---------------------------------------------------------------------------
__global__ __launch_bounds__(704) void intent_kernel(
    const float* __restrict__ pooled,
    const float* __restrict__ W_id,
    const float* __restrict__ b_id,
    float* __restrict__ out)
{
    int b    = blockIdx.x;
    int w    = threadIdx.x >> 5;   // 0..21 (output column)
    int lane = threadIdx.x & 31;

    const float* p = pooled + b * H_;
    float sum = 0.f;
    #pragma unroll 4
    for (int k = lane; k < H_; k += 32)
        sum += p[k] * W_id[k * INTENT_ + w];

    #pragma unroll
    for (int off = 16; off > 0; off >>= 1)
        sum += __shfl_xor_sync(0xFFFFFFFFu, sum, off);

    if (lane == 0)
        out[b * INTENT_ + w] = sum + b_id[w];
}

// ---------------------------------------------------------------------------
// Slot head: fused word-piece gather + GEMM.
//   mean_word[m] = 0.5 * (hidden[b, s] + hidden[b, s + l'])   (l'=0 if len==1)
//   res_sf = mean_word @ W_slot + b_slot    [26112, 122]
// Block tile 64x128, K-tile 16, 256 threads, 4x8 accumulators per thread.
// ---------------------------------------------------------------------------
__global__ __launch_bounds__(256) void slot_kernel(
    const float* __restrict__ hidden,
    const float* __restrict__ W_slot,
    const float* __restrict__ b_slot,
    const int*   __restrict__ starts,
    const int*   __restrict__ lens,
    float* __restrict__ out)
{
    __shared__ float As[BK][AS_STRIDE];   // A transposed: As[k][m]
    __shared__ float Bs[BK][BN];
    __shared__ int   off0_s[BM];
    __shared__ int   off1_s[BM];

    const int tid = threadIdx.x;
    const int m0  = blockIdx.x * BM;

    // Per-row gather metadata (uniform 0.5*(h0+h1) form).
    if (tid < BM) {
        int m = m0 + tid;                 // grid sized exactly -> always valid
        int b = m / NW_;
        int w = m - b * NW_;
        int s = starts[b * NW_ + w];
        int l = lens  [b * NW_ + w];
        int o0 = (b * S_ + s) * H_;
        off0_s[tid] = o0;
        off1_s[tid] = (l == 1) ? o0 : o0 + l * H_;   // len==1 -> duplicate row
    }
    __syncthreads();

    // A-load mapping: row r = tid/4, k-chunk kc = tid%4 (4 floats each).
    const int a_r  = tid >> 2;
    const int a_kc = (tid & 3) << 2;
    const int o0 = off0_s[a_r];
    const int o1 = off1_s[a_r];

    // compute mapping: tx in [0,16) -> 8 cols, ty in [0,16) -> 4 rows
    const int tx = tid & 15;
    const int ty = tid >> 4;

    float acc[4][8];
    #pragma unroll
    for (int i = 0; i < 4; i++)
        #pragma unroll
        for (int j = 0; j < 8; j++)
            acc[i][j] = 0.f;

    for (int kt = 0; kt < H_ / BK; kt++) {
        const int kbase = kt * BK;

        // --- load A tile (gather + mean), store transposed ---
        {
            float4 h0 = *reinterpret_cast<const float4*>(&hidden[o0 + kbase + a_kc]);
            float4 h1 = *reinterpret_cast<const float4*>(&hidden[o1 + kbase + a_kc]);
            As[a_kc + 0][a_r] = 0.5f * (h0.x + h1.x);
            As[a_kc + 1][a_r] = 0.5f * (h0.y + h1.y);
            As[a_kc + 2][a_r] = 0.5f * (h0.z + h1.z);
            As[a_kc + 3][a_r] = 0.5f * (h0.w + h1.w);
        }

        // --- load B tile: Bs[kk][n] = W_slot[kbase+kk][n], zero-pad n>=122 ---
        #pragma unroll
        for (int j = 0; j < (BK * BN) / 256; j++) {
            int e  = tid + j * 256;
            int kk = e >> 7;          // e / 128
            int n  = e & 127;
            Bs[kk][n] = (n < SLOT_) ? W_slot[(kbase + kk) * SLOT_ + n] : 0.f;
        }

        __syncthreads();

        // --- compute ---
        #pragma unroll
        for (int kk = 0; kk < BK; kk++) {
            float4 a  = *reinterpret_cast<const float4*>(&As[kk][ty * 4]);
            float4 b0 = *reinterpret_cast<const float4*>(&Bs[kk][tx * 8]);
            float4 b1 = *reinterpret_cast<const float4*>(&Bs[kk][tx * 8 + 4]);
            float av[4] = {a.x, a.y, a.z, a.w};
            float bv[8] = {b0.x, b0.y, b0.z, b0.w, b1.x, b1.y, b1.z, b1.w};
            #pragma unroll
            for (int i = 0; i < 4; i++)
                #pragma unroll
                for (int j = 0; j < 8; j++)
                    acc[i][j] = fmaf(av[i], bv[j], acc[i][j]);
        }

        __syncthreads();
    }

    // --- epilogue: add bias, write res_sf after res_id block ---
    #pragma unroll
    for (int i = 0; i < 4; i++) {
        int m = m0 + ty * 4 + i;
        #pragma unroll
        for (int j = 0; j < 8; j++) {
            int n = tx * 8 + j;
            if (n < SLOT_)
                out[OUT_ID_ELEMS + m * SLOT_ + n] = acc[i][j] + b_slot[n];
        }
    }
}

// ---------------------------------------------------------------------------
extern "C" void kernel_launch(void* const* d_in, const int* in_sizes, int n_in,
                              void* d_out, int out_size)
{
    const float* hidden  = (const float*)d_in[0];
    const float* pooled  = (const float*)d_in[1];
    const float* W_id    = (const float*)d_in[2];
    const float* b_id    = (const float*)d_in[3];
    const float* W_slot  = (const float*)d_in[4];
    const float* b_slot  = (const float*)d_in[5];
    const int*   starts  = (const int*)d_in[6];
    const int*   lens    = (const int*)d_in[7];
    float* out = (float*)d_out;

    intent_kernel<<<B_, 704>>>(pooled, W_id, b_id, out);
    slot_kernel<<<M_TOTAL / BM, 256>>>(hidden, W_slot, b_slot, starts, lens, out);
}

// round 3
// speedup vs baseline: 1.7147x; 1.7147x over previous
#include <cuda_runtime.h>
#include <cuda_bf16.h>

// Problem constants
#define B_      512
#define S_      128
#define H_      768
#define NW_     51
#define INTENT_ 22
#define SLOT_   122

// Slot GEMM tiling: 64x128 block tile, 128 threads, 8x8 per thread
#define BM   64
#define BN   128
#define BK   16
#define ASP  68                 // As row stride (floats), 16B-aligned rows
#define NKT  (H_ / BK)          // 48 k-tiles

#define M_TOTAL      (B_ * NW_)      // 26112
#define OUT_ID_ELEMS (B_ * INTENT_)  // 11264

// Padded copy of W_slot: [768][128], cols >=122 zero. Device-global scratch.
__device__ float W_pad[H_ * BN];

// ---------------------------------------------------------------------------
__global__ __launch_bounds__(128) void pad_kernel(const float* __restrict__ W_slot)
{
    int r = blockIdx.x;            // 0..767
    int t = threadIdx.x;           // 0..127
    W_pad[r * BN + t] = (t < SLOT_) ? W_slot[r * SLOT_ + t] : 0.f;
}

// ---------------------------------------------------------------------------
// Intent head: res_id = pooled @ W_id + b_id   [512, 22]
// ---------------------------------------------------------------------------
__global__ __launch_bounds__(704) void intent_kernel(
    const float* __restrict__ pooled,
    const float* __restrict__ W_id,
    const float* __restrict__ b_id,
    float* __restrict__ out)
{
    int b    = blockIdx.x;
    int w    = threadIdx.x >> 5;   // 0..21
    int lane = threadIdx.x & 31;

    const float* p = pooled + b * H_;
    float sum = 0.f;
    #pragma unroll 4
    for (int k = lane; k < H_; k += 32)
        sum += p[k] * W_id[k * INTENT_ + w];

    #pragma unroll
    for (int off = 16; off > 0; off >>= 1)
        sum += __shfl_xor_sync(0xFFFFFFFFu, sum, off);

    if (lane == 0)
        out[b * INTENT_ + w] = sum + b_id[w];
}

// ---------------------------------------------------------------------------
__device__ __forceinline__ unsigned smem_u32(const void* p)
{
    return (unsigned)__cvta_generic_to_shared(p);
}

#define CP_ASYNC_16(dst, src) \
    asm volatile("cp.async.cg.shared.global [%0], [%1], 16;\n" :: "r"(dst), "l"(src))
#define CP_ASYNC_COMMIT() asm volatile("cp.async.commit_group;\n")
#define CP_ASYNC_WAIT0()  asm volatile("cp.async.wait_group 0;\n")

// ---------------------------------------------------------------------------
// Slot head: fused word-piece gather + GEMM with double-buffered smem.
//   mean_word[m] = 0.5 * (hidden[b,s] + hidden[b,s+l'])  (l'=0 if len==1)
//   res_sf = mean_word @ W_slot + b_slot
// 128 threads, 8x8 accumulators each, strided fragments (conflict-free LDS.128).
// ---------------------------------------------------------------------------
__global__ __launch_bounds__(128) void slot_kernel(
    const float* __restrict__ hidden,
    const float* __restrict__ b_slot,
    const int*   __restrict__ starts,
    const int*   __restrict__ lens,
    float* __restrict__ out)
{
    __shared__ float As[2][BK][ASP];   // A transposed: As[buf][k][m]
    __shared__ float Bs[2][BK][BN];
    __shared__ int   off0s[BM];
    __shared__ int   off1s[BM];

    const int tid = threadIdx.x;
    const int m0  = blockIdx.x * BM;

    if (tid < BM) {
        int m = m0 + tid;                    // grid exact -> always valid
        int b = m / NW_;
        int w = m - b * NW_;
        int s = starts[b * NW_ + w];
        int l = lens  [b * NW_ + w];
        int o0 = (b * S_ + s) * H_;
        off0s[tid] = o0;
        off1s[tid] = (l == 1) ? o0 : o0 + l * H_;   // len==1 -> duplicate row
    }
    __syncthreads();

    // A staging: thread -> row a_r, 8 consecutive k starting at a_kc
    const int a_r  = tid >> 1;
    const int a_kc = (tid & 1) * 8;
    const int o0 = off0s[a_r] + a_kc;
    const int o1 = off1s[a_r] + a_kc;

    // compute mapping: strided 8x8 fragment
    const int tx = tid & 15;       // cols tx*4 and 64+tx*4
    const int ty = tid >> 4;       // rows ty*4 and 32+ty*4

    float acc[8][8];
    #pragma unroll
    for (int i = 0; i < 8; i++)
        #pragma unroll
        for (int j = 0; j < 8; j++)
            acc[i][j] = 0.f;

    // ---- prologue: fill buffer 0 ----
    {
        #pragma unroll
        for (int j = 0; j < 4; j++) {
            int idx = (tid + j * 128) * 4;
            int k = idx >> 7, n = idx & 127;
            CP_ASYNC_16(smem_u32(&Bs[0][k][n]), &W_pad[k * BN + n]);
        }
        CP_ASYNC_COMMIT();

        float4 h0a = *reinterpret_cast<const float4*>(&hidden[o0]);
        float4 h0b = *reinterpret_cast<const float4*>(&hidden[o0 + 4]);
        float4 h1a = *reinterpret_cast<const float4*>(&hidden[o1]);
        float4 h1b = *reinterpret_cast<const float4*>(&hidden[o1 + 4]);
        As[0][a_kc + 0][a_r] = 0.5f * (h0a.x + h1a.x);
        As[0][a_kc + 1][a_r] = 0.5f * (h0a.y + h1a.y);
        As[0][a_kc + 2][a_r] = 0.5f * (h0a.z + h1a.z);
        As[0][a_kc + 3][a_r] = 0.5f * (h0a.w + h1a.w);
        As[0][a_kc + 4][a_r] = 0.5f * (h0b.x + h1b.x);
        As[0][a_kc + 5][a_r] = 0.5f * (h0b.y + h1b.y);
        As[0][a_kc + 6][a_r] = 0.5f * (h0b.z + h1b.z);
        As[0][a_kc + 7][a_r] = 0.5f * (h0b.w + h1b.w);

        CP_ASYNC_WAIT0();
        __syncthreads();
    }

    // ---- main loop ----
    for (int kt = 0; kt < NKT; kt++) {
        const int cur = kt & 1;
        const int nxt = cur ^ 1;

        float4 p0a, p0b, p1a, p1b;
        if (kt < NKT - 1) {
            const int kb = (kt + 1) * BK;
            #pragma unroll
            for (int j = 0; j < 4; j++) {
                int idx = (tid + j * 128) * 4;
                int k = idx >> 7, n = idx & 127;
                CP_ASYNC_16(smem_u32(&Bs[nxt][k][n]), &W_pad[(kb + k) * BN + n]);
            }
            CP_ASYNC_COMMIT();
            p0a = *reinterpret_cast<const float4*>(&hidden[o0 + kb]);
            p0b = *reinterpret_cast<const float4*>(&hidden[o0 + kb + 4]);
            p1a = *reinterpret_cast<const float4*>(&hidden[o1 + kb]);
            p1b = *reinterpret_cast<const float4*>(&hidden[o1 + kb + 4]);
        }

        #pragma unroll
        for (int kk = 0; kk < BK; kk++) {
            float4 a0 = *reinterpret_cast<const float4*>(&As[cur][kk][ty * 4]);
            float4 a1 = *reinterpret_cast<const float4*>(&As[cur][kk][32 + ty * 4]);
            float4 b0 = *reinterpret_cast<const float4*>(&Bs[cur][kk][tx * 4]);
            float4 b1 = *reinterpret_cast<const float4*>(&Bs[cur][kk][64 + tx * 4]);
            float av[8] = {a0.x, a0.y, a0.z, a0.w, a1.x, a1.y, a1.z, a1.w};
            float bv[8] = {b0.x, b0.y, b0.z, b0.w, b1.x, b1.y, b1.z, b1.w};
            #pragma unroll
            for (int i = 0; i < 8; i++)
                #pragma unroll
                for (int j = 0; j < 8; j++)
                    acc[i][j] = fmaf(av[i], bv[j], acc[i][j]);
        }

        if (kt < NKT - 1) {
            As[nxt][a_kc + 0][a_r] = 0.5f * (p0a.x + p1a.x);
            As[nxt][a_kc + 1][a_r] = 0.5f * (p0a.y + p1a.y);
            As[nxt][a_kc + 2][a_r] = 0.5f * (p0a.z + p1a.z);
            As[nxt][a_kc + 3][a_r] = 0.5f * (p0a.w + p1a.w);
            As[nxt][a_kc + 4][a_r] = 0.5f * (p0b.x + p1b.x);
            As[nxt][a_kc + 5][a_r] = 0.5f * (p0b.y + p1b.y);
            As[nxt][a_kc + 6][a_r] = 0.5f * (p0b.z + p1b.z);
            As[nxt][a_kc + 7][a_r] = 0.5f * (p0b.w + p1b.w);
            CP_ASYNC_WAIT0();
        }
        __syncthreads();
    }

    // ---- epilogue: bias + vectorized store ----
    // Column groups: lo = tx*4 (always < 122 since tx*4 <= 60),
    //                hi = 64 + tx*4 (valid while < 122; tx==14 -> 120..123 partial, tx==15 -> 124 none)
    float4 bl = *reinterpret_cast<const float4*>(&b_slot[tx * 4]);
    int hn = 64 + tx * 4;
    float bh0 = (hn + 0 < SLOT_) ? __ldg(&b_slot[hn + 0]) : 0.f;
    float bh1 = (hn + 1 < SLOT_) ? __ldg(&b_slot[hn + 1]) : 0.f;
    float bh2 = (hn + 2 < SLOT_) ? __ldg(&b_slot[hn + 2]) : 0.f;
    float bh3 = (hn + 3 < SLOT_) ? __ldg(&b_slot[hn + 3]) : 0.f;

    #pragma unroll
    for (int hi = 0; hi < 2; hi++) {
        #pragma unroll
        for (int ii = 0; ii < 4; ii++) {
            int m = m0 + hi * 32 + ty * 4 + ii;
            float* orow = out + OUT_ID_ELEMS + m * SLOT_;
            // low group: full float4 (unaligned base 122*m -> use scalar-safe stores)
            float* pl = orow + tx * 4;
            pl[0] = acc[hi * 4 + ii][0] + bl.x;
            pl[1] = acc[hi * 4 + ii][1] + bl.y;
            pl[2] = acc[hi * 4 + ii][2] + bl.z;
            pl[3] = acc[hi * 4 + ii][3] + bl.w;
            // high group: predicated tail
            float* ph = orow + hn;
            if (hn + 0 < SLOT_) ph[0] = acc[hi * 4 + ii][4] + bh0;
            if (hn + 1 < SLOT_) ph[1] = acc[hi * 4 + ii][5] + bh1;
            if (hn + 2 < SLOT_) ph[2] = acc[hi * 4 + ii][6] + bh2;
            if (hn + 3 < SLOT_) ph[3] = acc[hi * 4 + ii][7] + bh3;
        }
    }
}

// ---------------------------------------------------------------------------
extern "C" void kernel_launch(void* const* d_in, const int* in_sizes, int n_in,
                              void* d_out, int out_size)
{
    const float* hidden  = (const float*)d_in[0];
    const float* pooled  = (const float*)d_in[1];
    const float* W_id    = (const float*)d_in[2];
    const float* b_id    = (const float*)d_in[3];
    const float* W_slot  = (const float*)d_in[4];
    const float* b_slot  = (const float*)d_in[5];
    const int*   starts  = (const int*)d_in[6];
    const int*   lens    = (const int*)d_in[7];
    float* out = (float*)d_out;

    pad_kernel<<<H_, 128>>>(W_slot);
    intent_kernel<<<B_, 704>>>(pooled, W_id, b_id, out);
    slot_kernel<<<M_TOTAL / BM, 128>>>(hidden, b_slot, starts, lens, out);
}

// round 8
// speedup vs baseline: 2.4079x; 1.4043x over previous
#include <cuda_runtime.h>
#include <cuda_bf16.h>
#include <cstdint>

// Problem constants
#define B_      512
#define S_      128
#define H_      768
#define NW_     51
#define INTENT_ 22
#define SLOT_   122

#define M_TOTAL      (B_ * NW_)      // 26112
#define OUT_ID_ELEMS (B_ * INTENT_)  // 11264

// Slot GEMM config (mma.sync m16n8k16 bf16, 3-term split)
#define BM      64
#define KC      64                   // K per chunk
#define CHUNKS  (H_ / KC)            // 12
#define K16     (H_ / 16)            // 48 k16 steps total
#define NBLK    (M_TOTAL / BM)       // 408
#define NT8     16                   // n8 tiles over padded N=128

// Pre-baked B fragments: [k16 step][n8 tile][lane] -> {b0,b1}
__device__ uint2 Bh_frag[K16 * NT8 * 32];
__device__ uint2 Bl_frag[K16 * NT8 * 32];

// ---------------------------------------------------------------------------
__device__ __forceinline__ uint32_t sw128(uint32_t off) {
    return off ^ ((off >> 3) & 0x70);
}
__device__ __forceinline__ uint32_t smem_u32(const void* p) {
    return (uint32_t)__cvta_generic_to_shared(p);
}
// pack two fp32 -> bf16x2 (lo = first arg)
__device__ __forceinline__ uint32_t cvt_bf2(float lo, float hi) {
    uint32_t r;
    asm("cvt.rn.bf16x2.f32 %0, %1, %2;" : "=r"(r) : "f"(hi), "f"(lo));
    return r;
}
__device__ __forceinline__ void ldm4(uint32_t* r, uint32_t addr) {
    asm volatile("ldmatrix.sync.aligned.m8n8.x4.shared.b16 {%0,%1,%2,%3}, [%4];"
                 : "=r"(r[0]), "=r"(r[1]), "=r"(r[2]), "=r"(r[3]) : "r"(addr));
}
__device__ __forceinline__ void mma_bf16(float* c, const uint32_t* a, uint2 b) {
    asm volatile(
        "mma.sync.aligned.m16n8k16.row.col.f32.bf16.bf16.f32 "
        "{%0,%1,%2,%3}, {%4,%5,%6,%7}, {%8,%9}, {%0,%1,%2,%3};"
        : "+f"(c[0]), "+f"(c[1]), "+f"(c[2]), "+f"(c[3])
        : "r"(a[0]), "r"(a[1]), "r"(a[2]), "r"(a[3]), "r"(b.x), "r"(b.y));
}

// ---------------------------------------------------------------------------
// Prep: bake W_slot into per-lane mma B fragments (hi/lo bf16 split).
// e -> (s, j, l): n = j*8 + l/4, k = s*16 + (l%4)*2; b0 = k,k+1; b1 = k+8,k+9.
// ---------------------------------------------------------------------------
__global__ __launch_bounds__(256) void prep_kernel(const float* __restrict__ W_slot)
{
    int e = blockIdx.x * 256 + threadIdx.x;    // [0, 48*16*32)
    int s = e >> 9;
    int j = (e >> 5) & 15;
    int l = e & 31;
    int g = l >> 2, t = l & 3;
    int n = j * 8 + g;
    int k = s * 16 + t * 2;

    float v0 = 0.f, v1 = 0.f, v2 = 0.f, v3 = 0.f;
    if (n < SLOT_) {
        v0 = W_slot[(k + 0) * SLOT_ + n];
        v1 = W_slot[(k + 1) * SLOT_ + n];
        v2 = W_slot[(k + 8) * SLOT_ + n];
        v3 = W_slot[(k + 9) * SLOT_ + n];
    }
    uint32_t h0 = cvt_bf2(v0, v1);
    uint32_t h1 = cvt_bf2(v2, v3);
    float r0 = v0 - __uint_as_float(h0 << 16);
    float r1 = v1 - __uint_as_float(h0 & 0xFFFF0000u);
    float r2 = v2 - __uint_as_float(h1 << 16);
    float r3 = v3 - __uint_as_float(h1 & 0xFFFF0000u);
    Bh_frag[e] = make_uint2(h0, h1);
    Bl_frag[e] = make_uint2(cvt_bf2(r0, r1), cvt_bf2(r2, r3));
}

// ---------------------------------------------------------------------------
// Intent head: res_id = pooled @ W_id + b_id   [512, 22]
// ---------------------------------------------------------------------------
__global__ __launch_bounds__(704) void intent_kernel(
    const float* __restrict__ pooled,
    const float* __restrict__ W_id,
    const float* __restrict__ b_id,
    float* __restrict__ out)
{
    int b    = blockIdx.x;
    int w    = threadIdx.x >> 5;
    int lane = threadIdx.x & 31;

    const float* p = pooled + b * H_;
    float sum = 0.f;
    #pragma unroll 4
    for (int k = lane; k < H_; k += 32)
        sum += p[k] * W_id[k * INTENT_ + w];

    #pragma unroll
    for (int off = 16; off > 0; off >>= 1)
        sum += __shfl_xor_sync(0xFFFFFFFFu, sum, off);

    if (lane == 0)
        out[b * INTENT_ + w] = sum + b_id[w];
}

// ---------------------------------------------------------------------------
// Slot head: fused gather/mean + bf16-split mma.sync GEMM.
// 64x128 tile per CTA, 8 warps x (32m x 32n), double-buffered A in smem.
// ---------------------------------------------------------------------------
__global__ __launch_bounds__(256, 2) void slot_kernel(
    const float* __restrict__ hidden,
    const float* __restrict__ b_slot,
    const int*   __restrict__ starts,
    const int*   __restrict__ lens,
    float* __restrict__ out)
{
    // A tiles: [buf][term(hi/lo)] 64 rows x 128B, SW128-swizzled
    __shared__ __align__(1024) unsigned char Asm[2][2][BM * 128];
    __shared__ int off0s[BM];
    __shared__ int off1s[BM];

    const int tid  = threadIdx.x;
    const int w    = tid >> 5;
    const int l    = tid & 31;
    const int m0   = blockIdx.x * BM;

    if (tid < BM) {
        int m = m0 + tid;
        int b = m / NW_;
        int wd = m - b * NW_;
        int s = starts[b * NW_ + wd];
        int ln = lens [b * NW_ + wd];
        int o0 = (b * S_ + s) * H_;
        off0s[tid] = o0;
        off1s[tid] = (ln == 1) ? o0 : o0 + ln * H_;
    }
    __syncthreads();

    // A producer mapping: row = tid/4, k-quarter = tid%4 (16 floats)
    const int a_row = tid >> 2;
    const int a_q   = tid & 3;
    const int o0 = off0s[a_row] + a_q * 16;
    const int o1 = off1s[a_row] + a_q * 16;

    // warp compute mapping: 2 warps in m (32 rows), 4 in n (32 cols)
    const int wm  = (w & 1) * 32;
    const int jg0 = (w >> 1) * 4;            // first n8 tile
    const int g = l >> 2, t = l & 3;

    // ldmatrix per-lane geometry
    const int lr   = l & 7;
    const int sel  = l >> 3;
    const int arow0 = wm + (sel & 1) * 8 + lr;        // mtile i adds i*16
    const int kh16  = (sel >> 1) * 16;                // k-half byte offset

    float acc[2][4][4];
    #pragma unroll
    for (int i = 0; i < 2; i++)
        #pragma unroll
        for (int j = 0; j < 4; j++)
            #pragma unroll
            for (int q = 0; q < 4; q++) acc[i][j][q] = 0.f;

    float4 p0[4], p1[4];

    // ---- convert+store helper (expanded inline twice) ----
    #define CONVERT_STORE(BUF)                                                  \
    do {                                                                        \
        uint32_t hw[8], lw[8];                                                  \
        _Pragma("unroll")                                                       \
        for (int e = 0; e < 4; e++) {                                           \
            float a0 = 0.5f * (p0[e].x + p1[e].x);                              \
            float a1 = 0.5f * (p0[e].y + p1[e].y);                              \
            float a2 = 0.5f * (p0[e].z + p1[e].z);                              \
            float a3 = 0.5f * (p0[e].w + p1[e].w);                              \
            uint32_t h0 = cvt_bf2(a0, a1);                                      \
            uint32_t h1 = cvt_bf2(a2, a3);                                      \
            hw[e * 2 + 0] = h0;                                                 \
            hw[e * 2 + 1] = h1;                                                 \
            lw[e * 2 + 0] = cvt_bf2(a0 - __uint_as_float(h0 << 16),             \
                                    a1 - __uint_as_float(h0 & 0xFFFF0000u));    \
            lw[e * 2 + 1] = cvt_bf2(a2 - __uint_as_float(h1 << 16),             \
                                    a3 - __uint_as_float(h1 & 0xFFFF0000u));    \
        }                                                                       \
        uint32_t byte0 = sw128((uint32_t)(a_row * 128 + a_q * 32));             \
        uint32_t byte1 = sw128((uint32_t)(a_row * 128 + a_q * 32 + 16));        \
        *reinterpret_cast<uint4*>(&Asm[BUF][0][byte0]) = make_uint4(hw[0], hw[1], hw[2], hw[3]); \
        *reinterpret_cast<uint4*>(&Asm[BUF][0][byte1]) = make_uint4(hw[4], hw[5], hw[6], hw[7]); \
        *reinterpret_cast<uint4*>(&Asm[BUF][1][byte0]) = make_uint4(lw[0], lw[1], lw[2], lw[3]); \
        *reinterpret_cast<uint4*>(&Asm[BUF][1][byte1]) = make_uint4(lw[4], lw[5], lw[6], lw[7]); \
    } while (0)

    // ---- prologue: chunk 0 ----
    #pragma unroll
    for (int e = 0; e < 4; e++) {
        p0[e] = *reinterpret_cast<const float4*>(&hidden[o0 + e * 4]);
        p1[e] = *reinterpret_cast<const float4*>(&hidden[o1 + e * 4]);
    }
    CONVERT_STORE(0);
    __syncthreads();

    // ---- main loop ----
    for (int c = 0; c < CHUNKS; c++) {
        const int cur = c & 1;

        if (c < CHUNKS - 1) {
            const int kb = (c + 1) * KC;
            #pragma unroll
            for (int e = 0; e < 4; e++) {
                p0[e] = *reinterpret_cast<const float4*>(&hidden[o0 + kb + e * 4]);
                p1[e] = *reinterpret_cast<const float4*>(&hidden[o1 + kb + e * 4]);
            }
        }

        // mma over 4 k16 steps, B frags software-pipelined
        {
            const uint32_t ab_h = smem_u32(&Asm[cur][0][0]);
            const uint32_t ab_l = smem_u32(&Asm[cur][1][0]);
            uint2 bh[2][4], bl[2][4];

            #pragma unroll
            for (int j = 0; j < 4; j++) {
                int idx = ((c * 4 + 0) * NT8 + jg0 + j) * 32 + l;
                bh[0][j] = __ldg(&Bh_frag[idx]);
                bl[0][j] = __ldg(&Bl_frag[idx]);
            }

            #pragma unroll
            for (int s = 0; s < 4; s++) {
                const int pb = s & 1;
                if (s < 3) {
                    #pragma unroll
                    for (int j = 0; j < 4; j++) {
                        int idx = ((c * 4 + s + 1) * NT8 + jg0 + j) * 32 + l;
                        bh[pb ^ 1][j] = __ldg(&Bh_frag[idx]);
                        bl[pb ^ 1][j] = __ldg(&Bl_frag[idx]);
                    }
                }

                uint32_t ah[2][4], al[2][4];
                #pragma unroll
                for (int i = 0; i < 2; i++) {
                    uint32_t byte = sw128((uint32_t)((arow0 + i * 16) * 128 + s * 32 + kh16));
                    ldm4(ah[i], ab_h + byte);
                    ldm4(al[i], ab_l + byte);
                }

                #pragma unroll
                for (int i = 0; i < 2; i++)
                    #pragma unroll
                    for (int j = 0; j < 4; j++) {
                        mma_bf16(acc[i][j], ah[i], bh[pb][j]);
                        mma_bf16(acc[i][j], ah[i], bl[pb][j]);
                        mma_bf16(acc[i][j], al[i], bh[pb][j]);
                    }
            }
        }

        if (c < CHUNKS - 1)
            CONVERT_STORE(cur ^ 1);
        __syncthreads();
    }

    // ---- epilogue: bias + store ----
    #pragma unroll
    for (int i = 0; i < 2; i++) {
        const int rA = m0 + wm + i * 16 + g;
        const int rB = rA + 8;
        #pragma unroll
        for (int j = 0; j < 4; j++) {
            const int n = (w >> 1) * 32 + j * 8 + t * 2;
            if (n < SLOT_) {
                float bx = __ldg(&b_slot[n]);
                float by = __ldg(&b_slot[n + 1]);
                float2 vA = make_float2(acc[i][j][0] + bx, acc[i][j][1] + by);
                float2 vB = make_float2(acc[i][j][2] + bx, acc[i][j][3] + by);
                *reinterpret_cast<float2*>(&out[OUT_ID_ELEMS + rA * SLOT_ + n]) = vA;
                *reinterpret_cast<float2*>(&out[OUT_ID_ELEMS + rB * SLOT_ + n]) = vB;
            }
        }
    }
    #undef CONVERT_STORE
}

// ---------------------------------------------------------------------------
extern "C" void kernel_launch(void* const* d_in, const int* in_sizes, int n_in,
                              void* d_out, int out_size)
{
    const float* hidden  = (const float*)d_in[0];
    const float* pooled  = (const float*)d_in[1];
    const float* W_id    = (const float*)d_in[2];
    const float* b_id    = (const float*)d_in[3];
    const float* W_slot  = (const float*)d_in[4];
    const float* b_slot  = (const float*)d_in[5];
    const int*   starts  = (const int*)d_in[6];
    const int*   lens    = (const int*)d_in[7];
    float* out = (float*)d_out;

    prep_kernel<<<(K16 * NT8 * 32) / 256, 256>>>(W_slot);
    intent_kernel<<<B_, 704>>>(pooled, W_id, b_id, out);
    slot_kernel<<<NBLK, 256>>>(hidden, b_slot, starts, lens, out);
}